// round 1
// baseline (speedup 1.0000x reference)
#include <cuda_runtime.h>

// Problem constants (fixed by the reference)
namespace {
constexpr int H = 400, W = 400, C = 64, CO = 64;
constexpr int BS = 10;          // gather block size
constexpr int BST = 8;          // block stride
constexpr int HOUT = 398, WOUT = 398;
constexpr float EPS = 1e-3f;

__device__ __forceinline__ unsigned long long pack2(float lo, float hi) {
    unsigned long long r;
    asm("mov.b64 %0, {%1, %2};" : "=l"(r) : "f"(lo), "f"(hi));
    return r;
}
__device__ __forceinline__ void unpack2(unsigned long long v, float &lo, float &hi) {
    asm("mov.b64 {%0, %1}, %2;" : "=f"(lo), "=f"(hi) : "l"(v));
}
// Packed f32x2 FMA — Blackwell sm_100+ only, unreachable from plain C++ (ptxas
// never auto-fuses); doubles fp32 FMA throughput vs FFMA.
__device__ __forceinline__ unsigned long long fma2(unsigned long long a,
                                                   unsigned long long b,
                                                   unsigned long long c) {
    unsigned long long d;
    asm("fma.rn.f32x2 %0, %1, %2, %3;" : "=l"(d) : "l"(a), "l"(b), "l"(c));
    return d;
}
} // namespace

// ---------------------------------------------------------------------------
// Kernel 1: zero the output (harness poisons it with 0xAA; the scatter only
// touches hi/wi in [0, 391], rest must be 0).
// ---------------------------------------------------------------------------
__global__ void zero_kernel(float4* __restrict__ o4, int n4,
                            float* __restrict__ o, int n) {
    int i = blockIdx.x * blockDim.x + threadIdx.x;
    int stride = gridDim.x * blockDim.x;
    const float4 z = make_float4(0.f, 0.f, 0.f, 0.f);
    for (; i < n4; i += stride) o4[i] = z;
    // scalar tail (out_size is divisible by 4 here, but stay general)
    int tail = n - (n4 << 2);
    if (blockIdx.x == 0 && threadIdx.x < tail) o[(n4 << 2) + threadIdx.x] = 0.f;
}

// ---------------------------------------------------------------------------
// Kernel 2: one CTA per active block.
//  - 128 threads stage the 10x10x64 tile into smem ([pos][cin], float4 loads,
//    __ldcs to keep L1 free for weights)
//  - thread t: h = t>>4 (output row 0..7), cg = t&15 (couts cg*4 .. cg*4+3)
//    computes 8 positions x 4 couts = 16 f32x2 accumulators (pairs over cout)
//  - weights read through __ldg (147 KB, L1-resident, reused by all CTAs)
//  - epilogue folds conv bias + BN into scale/bias, ReLU, STG.128 scatter
// ---------------------------------------------------------------------------
__global__ __launch_bounds__(128)
void conv_kernel(const float* __restrict__ x,
                 const float* __restrict__ wgt,     // [3][3][64][64] HWIO
                 const float* __restrict__ convb,   // [64]
                 const float* __restrict__ gamma,
                 const float* __restrict__ beta,
                 const float* __restrict__ mean,
                 const float* __restrict__ var,
                 const int*   __restrict__ idx,     // [NB][3] (n, by, bx)
                 float* __restrict__ out,
                 int nb) {
    int b = blockIdx.x;
    if (b >= nb) return;

    const int n  = idx[b * 3 + 0];
    const int by = idx[b * 3 + 1];
    const int bx = idx[b * 3 + 2];

    __shared__ __align__(16) float tile[BS * BS * C];   // 25.6 KB, [pos][cin]

    const int t = threadIdx.x;

    // --- stage tile: 1600 float4 (16 float4 per position) ---
    {
        const float* xb = x + ((n * H + by * BST) * W + bx * BST) * C;
        float4* t4 = reinterpret_cast<float4*>(tile);
        #pragma unroll
        for (int k = 0; k < 13; k++) {            // ceil(1600/128) = 13
            int i = t + k * 128;
            if (i < 1600) {
                int pos = i >> 4;                  // 0..99
                int c4  = i & 15;
                int ph = pos / 10;
                int pw = pos - ph * 10;
                t4[i] = __ldcs(reinterpret_cast<const float4*>(
                            xb + (ph * W + pw) * C + c4 * 4));
            }
        }
    }
    __syncthreads();

    const int h  = t >> 4;     // output row 0..7
    const int cg = t & 15;     // cout group: couts cg*4 .. cg*4+3

    unsigned long long acc[8][2];
    #pragma unroll
    for (int p = 0; p < 8; p++) { acc[p][0] = 0ull; acc[p][1] = 0ull; }

    const float4* tile4 = reinterpret_cast<const float4*>(tile);

    for (int kh = 0; kh < 3; kh++) {
        for (int kw = 0; kw < 3; kw++) {
            const int base = (h + kh) * 10 + kw;              // tile row of p=0
            const float* wp = wgt + ((kh * 3 + kw) * 64) * 64 + cg * 4;
            #pragma unroll 2
            for (int c4 = 0; c4 < 16; c4++) {
                // 4 cins worth of weights for our 4 couts -> 4 f32x2 pairs x2
                unsigned long long wq[4][2];
                #pragma unroll
                for (int u = 0; u < 4; u++) {
                    float4 wv = __ldg(reinterpret_cast<const float4*>(
                                    wp + (c4 * 4 + u) * 64));
                    wq[u][0] = pack2(wv.x, wv.y);
                    wq[u][1] = pack2(wv.z, wv.w);
                }
                #pragma unroll
                for (int p = 0; p < 8; p++) {
                    float4 xq = tile4[(base + p) * 16 + c4];  // 4 cins at pos
                    unsigned long long xs;
                    xs = pack2(xq.x, xq.x);
                    acc[p][0] = fma2(xs, wq[0][0], acc[p][0]);
                    acc[p][1] = fma2(xs, wq[0][1], acc[p][1]);
                    xs = pack2(xq.y, xq.y);
                    acc[p][0] = fma2(xs, wq[1][0], acc[p][0]);
                    acc[p][1] = fma2(xs, wq[1][1], acc[p][1]);
                    xs = pack2(xq.z, xq.z);
                    acc[p][0] = fma2(xs, wq[2][0], acc[p][0]);
                    acc[p][1] = fma2(xs, wq[2][1], acc[p][1]);
                    xs = pack2(xq.w, xq.w);
                    acc[p][0] = fma2(xs, wq[3][0], acc[p][0]);
                    acc[p][1] = fma2(xs, wq[3][1], acc[p][1]);
                }
            }
        }
    }

    // --- epilogue: fold conv bias + BN into scale/bias, ReLU, scatter ---
    float sc[4], bi[4];
    #pragma unroll
    for (int j = 0; j < 4; j++) {
        int c = cg * 4 + j;
        float s = gamma[c] * rsqrtf(var[c] + EPS);
        sc[j] = s;
        bi[j] = (convb[c] - mean[c]) * s + beta[c];
    }

    const int ho = by * BST + h;
    const int obase = ((n * HOUT + ho) * WOUT + bx * BST) * CO + cg * 4;
    #pragma unroll
    for (int p = 0; p < 8; p++) {
        float v0, v1, v2, v3;
        unpack2(acc[p][0], v0, v1);
        unpack2(acc[p][1], v2, v3);
        float4 o;
        o.x = fmaxf(fmaf(v0, sc[0], bi[0]), 0.f);
        o.y = fmaxf(fmaf(v1, sc[1], bi[1]), 0.f);
        o.z = fmaxf(fmaf(v2, sc[2], bi[2]), 0.f);
        o.w = fmaxf(fmaf(v3, sc[3], bi[3]), 0.f);
        *reinterpret_cast<float4*>(out + obase + p * CO) = o;
    }
}

// ---------------------------------------------------------------------------
extern "C" void kernel_launch(void* const* d_in, const int* in_sizes, int n_in,
                              void* d_out, int out_size) {
    const float* x     = (const float*)d_in[0];
    const float* wgt   = (const float*)d_in[1];
    const float* convb = (const float*)d_in[2];
    const float* gamma = (const float*)d_in[3];
    const float* beta  = (const float*)d_in[4];
    const float* mean  = (const float*)d_in[5];
    const float* var   = (const float*)d_in[6];
    const int*   idx   = (const int*)d_in[7];
    const int nb = in_sizes[7] / 3;
    float* out = (float*)d_out;

    const int n4 = out_size >> 2;
    zero_kernel<<<4736, 256>>>(reinterpret_cast<float4*>(out), n4, out, out_size);
    conv_kernel<<<nb, 128>>>(x, wgt, convb, gamma, beta, mean, var, idx, out, nb);
}

// round 3
// speedup vs baseline: 4.2740x; 4.2740x over previous
#include <cuda_runtime.h>
#include <cuda_fp16.h>
#include <cstdint>

// ---------------------------------------------------------------------------
// SparseBlock 3x3 valid conv + BN + ReLU as implicit GEMM on baseline-ISA
// tensor cores (mma.sync.m16n8k16.f32.f16.f16.f32 + ldmatrix).
// CTA = 256 threads = 4 active blocks: M=256 positions, N=64 couts, K=576.
// ---------------------------------------------------------------------------

namespace {
constexpr int H = 400, W = 400, C = 64, CO = 64;
constexpr int BST = 8;
constexpr int HOUT = 398, WOUT = 398;
constexpr float EPS = 1e-3f;

constexpr int KP = 584;                    // padded B row length (halves); 1168B = 73*16B (odd mod 8)
constexpr int B_BYTES = 64 * KP * 2;       // 74752
constexpr int SM_SC   = 0;                 // 64 floats (BN scale)
constexpr int SM_BI   = 256;               // 64 floats (BN bias)
constexpr int SM_B    = 512;               // weight image
constexpr int SM_TILE = SM_B + B_BYTES;    // 75264
constexpr int TILE_STRIDE = 144;           // bytes per position row (9*16B, odd mod 8)
constexpr int TILE_B  = 100 * TILE_STRIDE; // 14400 per block
constexpr int SMEM_TOTAL = SM_TILE + 4 * TILE_B;  // 132864

__device__ __forceinline__ uint32_t smem_u32(const void* p) {
    uint32_t a;
    asm("{ .reg .u64 t; cvta.to.shared.u64 t, %1; cvt.u32.u64 %0, t; }"
        : "=r"(a) : "l"(p));
    return a;
}
__device__ __forceinline__ void ldsm_x4(uint32_t* r, uint32_t addr) {
    asm volatile("ldmatrix.sync.aligned.m8n8.x4.shared.b16 {%0,%1,%2,%3}, [%4];"
                 : "=r"(r[0]), "=r"(r[1]), "=r"(r[2]), "=r"(r[3]) : "r"(addr));
}
__device__ __forceinline__ void mma16816(float* d, const uint32_t* a,
                                         uint32_t b0, uint32_t b1) {
    asm volatile(
        "mma.sync.aligned.m16n8k16.row.col.f32.f16.f16.f32 "
        "{%0,%1,%2,%3},{%4,%5,%6,%7},{%8,%9},{%0,%1,%2,%3};"
        : "+f"(d[0]), "+f"(d[1]), "+f"(d[2]), "+f"(d[3])
        : "r"(a[0]), "r"(a[1]), "r"(a[2]), "r"(a[3]), "r"(b0), "r"(b1));
}
} // namespace

// Pre-converted fp16 weight image [cout][k], row stride KP halves.
__device__ __align__(16) unsigned char g_wB[B_BYTES];

// ---------------------------------------------------------------------------
// Weight prep: wgt linear = [s][cin][cout] fp32 -> g_wB[cout][s*64+cin] fp16.
// ---------------------------------------------------------------------------
__global__ void wprep_kernel(const float* __restrict__ wgt) {
    int i = blockIdx.x * 256 + threadIdx.x;
    if (i >= 9 * 64 * 64) return;
    int cout = i & 63;
    int cin  = (i >> 6) & 63;
    int s    = i >> 12;
    reinterpret_cast<__half*>(g_wB)[cout * KP + s * 64 + cin] =
        __float2half(wgt[i]);
}

// ---------------------------------------------------------------------------
__global__ void zero_kernel(float4* __restrict__ o4, int n4) {
    int i = blockIdx.x * blockDim.x + threadIdx.x;
    int stride = gridDim.x * blockDim.x;
    const float4 z = make_float4(0.f, 0.f, 0.f, 0.f);
    for (; i < n4; i += stride) o4[i] = z;
}

// ---------------------------------------------------------------------------
__global__ __launch_bounds__(256)
void conv_kernel(const float* __restrict__ x,
                 const float* __restrict__ convb,
                 const float* __restrict__ gamma,
                 const float* __restrict__ beta,
                 const float* __restrict__ mean,
                 const float* __restrict__ var,
                 const int*   __restrict__ idx,
                 float* __restrict__ out,
                 int nb) {
    extern __shared__ __align__(16) unsigned char smem[];
    const uint32_t sb = smem_u32(smem);
    const int t = threadIdx.x;
    const int lane = t & 31;
    const int warp = t >> 5;

    // BN fold
    if (t < 64) {
        float s = gamma[t] * rsqrtf(var[t] + EPS);
        reinterpret_cast<float*>(smem + SM_SC)[t] = s;
        reinterpret_cast<float*>(smem + SM_BI)[t] = fmaf(convb[t] - mean[t], s, beta[t]);
    }

    // B image -> smem: 74752 B = 4672 uint4
    {
        const uint4* src = reinterpret_cast<const uint4*>(g_wB);
        uint4* dst = reinterpret_cast<uint4*>(smem + SM_B);
        #pragma unroll
        for (int k = 0; k < 19; k++) {
            int i = t + 256 * k;
            if (i < 4672) dst[i] = src[i];
        }
    }

    // Gather 4 tiles (10x10x64 fp32 -> fp16), row stride 144 B
    const int gb0 = blockIdx.x * 4;
    const float* xb[4];
    #pragma unroll
    for (int b = 0; b < 4; b++) {
        if (gb0 + b < nb) {
            int n  = __ldg(idx + (gb0 + b) * 3 + 0);
            int by = __ldg(idx + (gb0 + b) * 3 + 1);
            int bx = __ldg(idx + (gb0 + b) * 3 + 2);
            xb[b] = x + ((n * H + by * BST) * W + bx * BST) * C;
        } else xb[b] = x;  // dummy in-range, result discarded
    }
    #pragma unroll
    for (int k = 0; k < 25; k++) {
        int i = t + 256 * k;                  // 0..6399
        int tile = i / 1600;
        int j = i - tile * 1600;
        int pos = j >> 4;                     // 0..99
        int c4  = j & 15;
        int ph = pos / 10, pw = pos - (pos / 10) * 10;
        float4 v = __ldcs(reinterpret_cast<const float4*>(
                       xb[tile] + (ph * W + pw) * C + c4 * 4));
        __half2 h0 = __floats2half2_rn(v.x, v.y);
        __half2 h1 = __floats2half2_rn(v.z, v.w);
        uint2 pk = make_uint2(*reinterpret_cast<uint32_t*>(&h0),
                              *reinterpret_cast<uint32_t*>(&h1));
        *reinterpret_cast<uint2*>(smem + SM_TILE + tile * TILE_B
                                  + pos * TILE_STRIDE + c4 * 8) = pk;
    }
    __syncthreads();

    // ---- MMA mainloop ----
    const int bidx  = warp >> 1;   // block within CTA (0..3)
    const int mhalf = warp & 1;    // rows 0-31 or 32-63 of the block
    const uint32_t tbase = sb + SM_TILE + bidx * TILE_B;

    // A lane addresses (per m16 tile): row = (lane&15)+mt*16 -> position
    uint32_t a_addr[2];
    #pragma unroll
    for (int mt = 0; mt < 2; mt++) {
        int r = (lane & 15) + mt * 16;
        int pos = mhalf * 32 + r;
        int h = pos >> 3, w = pos & 7;
        a_addr[mt] = tbase + (h * 10 + w) * TILE_STRIDE + (lane >> 4) * 16;
    }
    // B lane address: n row + k-halfword select
    const uint32_t bn = (lane & 7) + ((lane >> 4) << 3);
    const uint32_t b_addr = sb + SM_B + bn * (KP * 2) + ((lane >> 3) & 1) * 16;

    const int soff[9] = {0, 1, 2, 10, 11, 12, 20, 21, 22};

    float acc[2][8][4];
    #pragma unroll
    for (int mt = 0; mt < 2; mt++)
        #pragma unroll
        for (int nt = 0; nt < 8; nt++)
            #pragma unroll
            for (int e = 0; e < 4; e++) acc[mt][nt][e] = 0.f;

    #pragma unroll
    for (int s = 0; s < 9; s++) {
        const uint32_t a0s = a_addr[0] + soff[s] * TILE_STRIDE;
        const uint32_t a1s = a_addr[1] + soff[s] * TILE_STRIDE;
        const uint32_t bs  = b_addr + s * 128;     // k-offset: s*64 halves
        #pragma unroll
        for (int c16 = 0; c16 < 4; c16++) {
            uint32_t af0[4], af1[4];
            ldsm_x4(af0, a0s + c16 * 32);
            ldsm_x4(af1, a1s + c16 * 32);
            uint32_t bf[16];
            #pragma unroll
            for (int j = 0; j < 4; j++)
                ldsm_x4(bf + 4 * j, bs + j * 16 * (KP * 2) + c16 * 32);
            #pragma unroll
            for (int nt = 0; nt < 8; nt++) {
                mma16816(acc[0][nt], af0, bf[nt * 2], bf[nt * 2 + 1]);
                mma16816(acc[1][nt], af1, bf[nt * 2], bf[nt * 2 + 1]);
            }
        }
    }

    // ---- epilogue: BN + ReLU + scatter ----
    const int gb = gb0 + bidx;
    if (gb < nb) {
        int n  = __ldg(idx + gb * 3 + 0);
        int by = __ldg(idx + gb * 3 + 1);
        int bx = __ldg(idx + gb * 3 + 2);
        const int g  = lane >> 2;
        const int cc = (lane & 3) * 2;
        const float2* sc2 = reinterpret_cast<const float2*>(smem + SM_SC);
        const float2* bi2 = reinterpret_cast<const float2*>(smem + SM_BI);
        #pragma unroll
        for (int mt = 0; mt < 2; mt++) {
            int pos0 = mhalf * 32 + mt * 16 + g;    // rows g and g+8
            int h0 = pos0 >> 3, w0 = pos0 & 7;
            float* op0 = out + (((n * HOUT + by * BST + h0) * WOUT) + bx * BST + w0) * CO;
            float* op1 = op0 + WOUT * CO;           // pos0+8 -> h0+1, same w
            #pragma unroll
            for (int nt = 0; nt < 8; nt++) {
                float2 s2 = sc2[nt * 4 + (lane & 3)];
                float2 b2 = bi2[nt * 4 + (lane & 3)];
                int col = nt * 8 + cc;
                float2 o0, o1;
                o0.x = fmaxf(fmaf(acc[mt][nt][0], s2.x, b2.x), 0.f);
                o0.y = fmaxf(fmaf(acc[mt][nt][1], s2.y, b2.y), 0.f);
                o1.x = fmaxf(fmaf(acc[mt][nt][2], s2.x, b2.x), 0.f);
                o1.y = fmaxf(fmaf(acc[mt][nt][3], s2.y, b2.y), 0.f);
                *reinterpret_cast<float2*>(op0 + col) = o0;
                *reinterpret_cast<float2*>(op1 + col) = o1;
            }
        }
    }
}

// ---------------------------------------------------------------------------
extern "C" void kernel_launch(void* const* d_in, const int* in_sizes, int n_in,
                              void* d_out, int out_size) {
    const float* x     = (const float*)d_in[0];
    const float* wgt   = (const float*)d_in[1];
    const float* convb = (const float*)d_in[2];
    const float* gamma = (const float*)d_in[3];
    const float* beta  = (const float*)d_in[4];
    const float* mean  = (const float*)d_in[5];
    const float* var   = (const float*)d_in[6];
    const int*   idx   = (const int*)d_in[7];
    const int nb = in_sizes[7] / 3;
    float* out = (float*)d_out;

    static bool attr_set = false;
    if (!attr_set) {
        cudaFuncSetAttribute(conv_kernel,
                             cudaFuncAttributeMaxDynamicSharedMemorySize, SMEM_TOTAL);
        attr_set = true;
    }

    wprep_kernel<<<(9 * 64 * 64 + 255) / 256, 256>>>(wgt);
    zero_kernel<<<4736, 256>>>(reinterpret_cast<float4*>(out), out_size >> 2);
    conv_kernel<<<(nb + 3) / 4, 256, SMEM_TOTAL>>>(
        x, convb, gamma, beta, mean, var, idx, out, nb);
}